// round 1
// baseline (speedup 1.0000x reference)
#include <cuda_runtime.h>
#include <cuda_bf16.h>

#define KB    4
#define RPTS  16384
#define KAPPA 32
#define NX    3
#define NF    13
#define NIN   16      // NX + NF
#define DOUT  64
#define NPTS  (KB * RPTS)   // 65536

// 16 MB scratch for Q = P @ H^T  (relu deferred: folded into max-with-0)
__device__ float g_Q[(size_t)NPTS * DOUT];

// ---------------------------------------------------------------------------
// Kernel 1: Q[k,r,d] = sum_j P[k,r,j] * H[d,j]
// One thread per (point,row d). Warps share a point row -> P loads broadcast.
// ---------------------------------------------------------------------------
__global__ void __launch_bounds__(256) compute_q_kernel(
    const float* __restrict__ X,   // [NPTS, NX]
    const float* __restrict__ F,   // [NPTS, NF]
    const float* __restrict__ H)   // [DOUT, NIN]
{
    int tid = blockIdx.x * 256 + threadIdx.x;
    if (tid >= NPTS * DOUT) return;
    int d   = tid & (DOUT - 1);
    int row = tid >> 6;

    const float* __restrict__ x = X + row * NX;
    const float* __restrict__ f = F + row * NF;
    const float* __restrict__ h = H + d * NIN;

    float acc = 0.f;
#pragma unroll
    for (int j = 0; j < NX; j++) acc += x[j] * h[j];
#pragma unroll
    for (int j = 0; j < NF; j++) acc += f[j] * h[NX + j];

    g_Q[tid] = acc;
}

// ---------------------------------------------------------------------------
// Kernel 2: per point r -- gather 32 Q rows, running max (init 0 == relu),
// then Y = relu(M @ gamma + bias). One warp per point, 8 warps per block.
// Lane l holds output dims (2l, 2l+1) during max phase (float2 gather),
// then dims (l, l+32) during the matvec.
// ---------------------------------------------------------------------------
#define WPB 8

__global__ void __launch_bounds__(WPB * 32) gather_max_gamma_kernel(
    const int*   __restrict__ N,      // [NPTS, KAPPA]
    const float* __restrict__ gamma,  // [DOUT, DOUT]  (gamma[d][e])
    const float* __restrict__ gbias,  // [DOUT]
    float*       __restrict__ out)    // [NPTS, DOUT]
{
    __shared__ float g_sh[DOUT * DOUT];     // 16 KB
    __shared__ float m_sh[WPB][DOUT];       // 2 KB

    const int tid = threadIdx.x;
    // cooperative load of gamma into shared
#pragma unroll
    for (int i = tid; i < DOUT * DOUT; i += WPB * 32) g_sh[i] = gamma[i];
    __syncthreads();

    const int warp  = tid >> 5;
    const int lane  = tid & 31;
    const int point = blockIdx.x * WPB + warp;       // k*R + r
    const int k     = point >> 14;                   // R = 16384

    // --- gather + max phase ---
    const int* __restrict__ nbr = N + (size_t)point * KAPPA;
    const int  my_idx = nbr[lane];                   // 32 indices, coalesced

    const float2* __restrict__ Qk =
        reinterpret_cast<const float2*>(g_Q + (size_t)k * RPTS * DOUT);

    float2 m = make_float2(0.f, 0.f);                // init 0 == fused relu
#pragma unroll
    for (int i = 0; i < KAPPA; i++) {
        int idx = __shfl_sync(0xffffffffu, my_idx, i);
        float2 v = Qk[idx * (DOUT / 2) + lane];      // 256 B coalesced per warp
        m.x = fmaxf(m.x, v.x);
        m.y = fmaxf(m.y, v.y);
    }

    m_sh[warp][2 * lane]     = m.x;
    m_sh[warp][2 * lane + 1] = m.y;
    __syncwarp();

    // --- gamma matvec: Y[e] = sum_d M[d] * gamma[d,e] + bias[e], relu ---
    float y0 = gbias[lane];
    float y1 = gbias[lane + 32];
#pragma unroll
    for (int d = 0; d < DOUT; d++) {
        float md = m_sh[warp][d];                    // broadcast, no conflict
        y0 += md * g_sh[d * DOUT + lane];
        y1 += md * g_sh[d * DOUT + lane + 32];
    }
    y0 = fmaxf(y0, 0.f);
    y1 = fmaxf(y1, 0.f);

    float* o = out + (size_t)point * DOUT;
    o[lane]      = y0;
    o[lane + 32] = y1;
}

// ---------------------------------------------------------------------------
extern "C" void kernel_launch(void* const* d_in, const int* in_sizes, int n_in,
                              void* d_out, int out_size)
{
    const float* X     = (const float*)d_in[0];
    const float* F     = (const float*)d_in[1];
    const int*   N     = (const int*)  d_in[2];
    const float* H     = (const float*)d_in[3];
    const float* gamma = (const float*)d_in[4];
    const float* gbias = (const float*)d_in[5];
    float*       out   = (float*)d_out;

    (void)in_sizes; (void)n_in; (void)out_size;

    // Kernel 1: Q = P @ H^T  (NPTS*DOUT threads)
    {
        int total  = NPTS * DOUT;
        int blocks = (total + 255) / 256;
        compute_q_kernel<<<blocks, 256>>>(X, F, H);
    }
    // Kernel 2: gather-max + gamma matvec
    {
        int blocks = NPTS / WPB;
        gather_max_gamma_kernel<<<blocks, WPB * 32>>>(N, gamma, gbias, out);
    }
}

// round 2
// speedup vs baseline: 1.8412x; 1.8412x over previous
#include <cuda_runtime.h>
#include <cuda_fp16.h>

#define KB    4
#define RPTS  16384
#define KAPPA 32
#define NX    3
#define NF    13
#define NIN   16
#define DOUT  64
#define NPTS  (KB * RPTS)   // 65536

// 8 MB fp16 scratch: Q[point][64] halves, one 128B line per row.
// Stored as uint4 so the gather can do 16B-aligned LDG.128.
__device__ uint4 g_Q4[(size_t)NPTS * 8];

// ---------------------------------------------------------------------------
// Kernel 1: Q[r,d] = sum_j P[r,j] * H[d,j], stored fp16.
// Warp per point (8 points / 256-thread block). Lane dp computes d=2dp,2dp+1.
// H transposed into shared as float2 -> conflict-free 64-bit LDS.
// ---------------------------------------------------------------------------
__global__ void __launch_bounds__(256) compute_q_kernel(
    const float* __restrict__ X,   // [NPTS, 3]
    const float* __restrict__ F,   // [NPTS, 13]
    const float* __restrict__ H)   // [64, 16]
{
    __shared__ float2 Hsh[NIN][32];   // Hsh[j][dp] = (H[2dp][j], H[2dp+1][j])

    const int tid = threadIdx.x;
    for (int idx = tid; idx < NIN * 32; idx += 256) {
        int j = idx >> 5, dp = idx & 31;
        Hsh[j][dp] = make_float2(H[(2 * dp) * NIN + j],
                                 H[(2 * dp + 1) * NIN + j]);
    }
    __syncthreads();

    const int row = blockIdx.x * 8 + (tid >> 5);   // one warp per point
    const int dp  = tid & 31;

    const float* __restrict__ x = X + (size_t)row * NX;
    const float* __restrict__ f = F + (size_t)row * NF;

    float p[NIN];
#pragma unroll
    for (int j = 0; j < NX; j++) p[j] = x[j];          // broadcast loads
#pragma unroll
    for (int j = 0; j < NF; j++) p[NX + j] = f[j];     // broadcast loads

    float2 acc = make_float2(0.f, 0.f);
#pragma unroll
    for (int j = 0; j < NIN; j++) {
        float2 h = Hsh[j][dp];
        acc.x += p[j] * h.x;
        acc.y += p[j] * h.y;
    }

    // halves land in order d = 0,1,...,63 ; 128B coalesced per warp
    ((__half2*)g_Q4)[(size_t)row * 32 + dp] = __floats2half2_rn(acc.x, acc.y);
}

// ---------------------------------------------------------------------------
// Kernel 2: gather 32 fp16 Q rows (1 line each), half2 running max (init 0 ==
// fused relu), butterfly-reduce, then Y = relu(M @ gamma + bias).
// Warp per point; each LDG.128 fetches 4 rows (8 lanes x 16B per row).
// ---------------------------------------------------------------------------
#define WPB 8

__device__ __forceinline__ __half2 hmax2_shfl_xor(__half2 v, int off) {
    unsigned u = __shfl_xor_sync(0xffffffffu, *(unsigned*)&v, off);
    return __hmax2(v, *(__half2*)&u);
}

__global__ void __launch_bounds__(WPB * 32) gather_max_gamma_kernel(
    const int*   __restrict__ Nbr,    // [NPTS, 32]
    const float* __restrict__ gamma,  // [64, 64]
    const float* __restrict__ gbias,  // [64]
    float*       __restrict__ out)    // [NPTS, 64]
{
    __shared__ float g_sh[DOUT * DOUT];   // 16 KB
    __shared__ float m_sh[WPB][DOUT];     // 2 KB

    const int tid = threadIdx.x;
    for (int i = tid; i < DOUT * DOUT; i += WPB * 32) g_sh[i] = gamma[i];
    __syncthreads();

    const int warp  = tid >> 5;
    const int lane  = tid & 31;
    const int point = blockIdx.x * WPB + warp;
    const int k     = point >> 14;                 // R = 16384

    const int my_idx = Nbr[(size_t)point * KAPPA + lane];  // coalesced

    const uint4* __restrict__ Qk = g_Q4 + (size_t)k * RPTS * 8;
    const int chunk = lane & 7;    // which 16B of the 128B row -> d=8c..8c+7
    const int rsel  = lane >> 3;   // which of 4 rows this lane helps fetch

    __half2 zero = __float2half2_rn(0.f);
    __half2 m0 = zero, m1 = zero, m2 = zero, m3 = zero;

#pragma unroll
    for (int i = 0; i < KAPPA / 4; i++) {          // 8 x LDG.128, 4 rows each
        int idx = __shfl_sync(0xffffffffu, my_idx, 4 * i + rsel);
        uint4 v = Qk[(size_t)idx * 8 + chunk];
        m0 = __hmax2(m0, *(__half2*)&v.x);
        m1 = __hmax2(m1, *(__half2*)&v.y);
        m2 = __hmax2(m2, *(__half2*)&v.z);
        m3 = __hmax2(m3, *(__half2*)&v.w);
    }

    // combine the 4 partial maxima (lanes differing in bits 3,4)
#pragma unroll
    for (int off = 8; off < 32; off <<= 1) {
        m0 = hmax2_shfl_xor(m0, off);
        m1 = hmax2_shfl_xor(m1, off);
        m2 = hmax2_shfl_xor(m2, off);
        m3 = hmax2_shfl_xor(m3, off);
    }

    if (lane < 8) {                 // lane holds d = 8*lane .. 8*lane+7
        float2 f0 = __half22float2(m0);
        float2 f1 = __half22float2(m1);
        float2 f2 = __half22float2(m2);
        float2 f3 = __half22float2(m3);
        float* m = &m_sh[warp][lane * 8];
        m[0] = f0.x; m[1] = f0.y; m[2] = f1.x; m[3] = f1.y;
        m[4] = f2.x; m[5] = f2.y; m[6] = f3.x; m[7] = f3.y;
    }
    __syncwarp();

    // --- gamma matvec: Y[e] = sum_d M[d] * gamma[d,e] + bias[e], relu ---
    float y0 = gbias[lane];
    float y1 = gbias[lane + 32];
#pragma unroll
    for (int d = 0; d < DOUT; d++) {
        float md = m_sh[warp][d];                  // broadcast
        y0 += md * g_sh[d * DOUT + lane];
        y1 += md * g_sh[d * DOUT + lane + 32];
    }
    y0 = fmaxf(y0, 0.f);
    y1 = fmaxf(y1, 0.f);

    float* o = out + (size_t)point * DOUT;
    o[lane]      = y0;
    o[lane + 32] = y1;
}

// ---------------------------------------------------------------------------
extern "C" void kernel_launch(void* const* d_in, const int* in_sizes, int n_in,
                              void* d_out, int out_size)
{
    const float* X     = (const float*)d_in[0];
    const float* F     = (const float*)d_in[1];
    const int*   Nbr   = (const int*)  d_in[2];
    const float* H     = (const float*)d_in[3];
    const float* gamma = (const float*)d_in[4];
    const float* gbias = (const float*)d_in[5];
    float*       out   = (float*)d_out;

    (void)in_sizes; (void)n_in; (void)out_size;

    compute_q_kernel<<<NPTS / 8, 256>>>(X, F, H);
    gather_max_gamma_kernel<<<NPTS / WPB, WPB * 32>>>(Nbr, gamma, gbias, out);
}

// round 3
// speedup vs baseline: 2.1827x; 1.1854x over previous
#include <cuda_runtime.h>
#include <cuda_fp16.h>

#define KB    4
#define RPTS  16384
#define KAPPA 32
#define NX    3
#define NF    13
#define NIN   16
#define DOUT  64
#define NPTS  (KB * RPTS)   // 65536

// 8 MB fp16 scratch: Q[point][64] halves; one 128B line per row (uint4 x 8).
__device__ uint4 g_Q4[(size_t)NPTS * 8];

// ---------------------------------------------------------------------------
// Kernel 1: Q[r,d] = sum_j P[r,j] * H[d,j], fp16 out.
// 32 points per 256-thread block. X/F staged coalesced into shared; H
// transposed in shared (broadcast LDS.128 reads); thread t owns point t>>3,
// output chunk t&7 (8 dims) -> one coalesced uint4 store per thread.
// ---------------------------------------------------------------------------
__global__ void __launch_bounds__(256) compute_q_kernel(
    const float* __restrict__ X,   // [NPTS, 3]
    const float* __restrict__ F,   // [NPTS, 13]
    const float* __restrict__ H)   // [64, 16]
{
    __shared__ float Psh[32][17];   // 32 points x 16 feats (pad 17)
    __shared__ float Ht[NIN][DOUT]; // Ht[j][d] = H[d][j]

    const int tid  = threadIdx.x;
    const int base = blockIdx.x * 32;         // first point of this block

    // coalesced stage of X (96 floats) and F (416 floats)
    if (tid < 96) {
        Psh[tid / 3][tid % 3] = X[(size_t)base * NX + tid];
    }
    for (int i = tid; i < 32 * NF; i += 256) {
        Psh[i / NF][NX + i % NF] = F[(size_t)base * NF + i];
    }
    // H transpose: consecutive tid -> consecutive d (conflict-free smem writes)
    for (int i = tid; i < NIN * DOUT; i += 256) {
        int d = i & 63, j = i >> 6;
        Ht[j][d] = H[d * NIN + j];
    }
    __syncthreads();

    const int p  = tid >> 3;      // local point 0..31
    const int c  = tid & 7;       // output chunk: d = 8c..8c+7
    const int d0 = c * 8;

    float acc[8] = {0.f, 0.f, 0.f, 0.f, 0.f, 0.f, 0.f, 0.f};
#pragma unroll
    for (int j = 0; j < NIN; j++) {
        float pj = Psh[p][j];                          // 8-lane broadcast
        float4 h0 = *(const float4*)&Ht[j][d0];        // broadcast 128B LDS
        float4 h1 = *(const float4*)&Ht[j][d0 + 4];
        acc[0] += pj * h0.x; acc[1] += pj * h0.y;
        acc[2] += pj * h0.z; acc[3] += pj * h0.w;
        acc[4] += pj * h1.x; acc[5] += pj * h1.y;
        acc[6] += pj * h1.z; acc[7] += pj * h1.w;
    }

    __half2 h01 = __floats2half2_rn(acc[0], acc[1]);
    __half2 h23 = __floats2half2_rn(acc[2], acc[3]);
    __half2 h45 = __floats2half2_rn(acc[4], acc[5]);
    __half2 h67 = __floats2half2_rn(acc[6], acc[7]);
    uint4 v;
    v.x = *(unsigned*)&h01; v.y = *(unsigned*)&h23;
    v.z = *(unsigned*)&h45; v.w = *(unsigned*)&h67;

    g_Q4[(size_t)(base + p) * 8 + c] = v;   // consecutive tid -> consecutive uint4
}

// ---------------------------------------------------------------------------
// Kernel 2: 4 points per warp. Gather 32 fp16 rows/point (LDG.128, 4 rows per
// instr), half2 running max (init 0 == fused relu), butterfly reduce, then
// Y = relu(M @ gamma + bias) with gamma as packed float2 in shared and the
// m[d] broadcast done via SHFL (no LDS broadcasts).
// ---------------------------------------------------------------------------
#define WPB 8
#define PPW 4

__global__ void __launch_bounds__(WPB * 32) gather_max_gamma_kernel(
    const int*   __restrict__ Nbr,    // [NPTS, 32]
    const float* __restrict__ gamma,  // [64, 64]
    const float* __restrict__ gbias,  // [64]
    float*       __restrict__ out)    // [NPTS, 64]
{
    __shared__ float2 gpk[DOUT][32];  // gpk[d][e] = (gamma[d][e], gamma[d][e+32])

    const int tid = threadIdx.x;
    for (int i = tid; i < DOUT * 32; i += WPB * 32) {
        int d = i >> 5, e = i & 31;
        gpk[d][e] = make_float2(gamma[d * DOUT + e], gamma[d * DOUT + e + 32]);
    }
    __syncthreads();

    const int warp   = tid >> 5;
    const int lane   = tid & 31;
    const int point0 = (blockIdx.x * WPB + warp) * PPW;
    const int k      = point0 >> 14;               // R = 16384

    int my_idx[PPW];
#pragma unroll
    for (int p = 0; p < PPW; p++)
        my_idx[p] = Nbr[(size_t)(point0 + p) * KAPPA + lane];

    const uint4* __restrict__ Qk = g_Q4 + (size_t)k * RPTS * 8;
    const int chunk = lane & 7;    // 16B chunk of the 128B row: d = 8c..8c+7
    const int rsel  = lane >> 3;   // which of 4 rows per LDG this lane fetches

    const __half2 zero = __float2half2_rn(0.f);
    __half2 m[PPW][4];
#pragma unroll
    for (int p = 0; p < PPW; p++) {
        m[p][0] = zero; m[p][1] = zero; m[p][2] = zero; m[p][3] = zero;
    }

#pragma unroll
    for (int p = 0; p < PPW; p++) {
#pragma unroll
        for (int i = 0; i < KAPPA / 4; i++) {      // 8 LDG.128, 4 rows each
            int idx = __shfl_sync(0xffffffffu, my_idx[p], 4 * i + rsel);
            uint4 v = Qk[(size_t)idx * 8 + chunk];
            m[p][0] = __hmax2(m[p][0], *(__half2*)&v.x);
            m[p][1] = __hmax2(m[p][1], *(__half2*)&v.y);
            m[p][2] = __hmax2(m[p][2], *(__half2*)&v.z);
            m[p][3] = __hmax2(m[p][3], *(__half2*)&v.w);
        }
    }

    // reduce the 4 rsel partials: after this every lane holds the true max
    // for its chunk: m[p][q] covers d = 8*(lane&7) + 2q (+1)
#pragma unroll
    for (int off = 8; off < 32; off <<= 1) {
#pragma unroll
        for (int p = 0; p < PPW; p++) {
#pragma unroll
            for (int q = 0; q < 4; q++) {
                unsigned u = __shfl_xor_sync(0xffffffffu, *(unsigned*)&m[p][q], off);
                m[p][q] = __hmax2(m[p][q], *(__half2*)&u);
            }
        }
    }

    // --- gamma matvec: Y[e] = relu( sum_d M[d]*gamma[d][e] + bias[e] ) ---
    float y0[PPW], y1[PPW];
    const float b0 = gbias[lane];
    const float b1 = gbias[lane + 32];
#pragma unroll
    for (int p = 0; p < PPW; p++) { y0[p] = b0; y1[p] = b1; }

#pragma unroll
    for (int d = 0; d < DOUT; d++) {
        const int src = d >> 3;          // lane holding this d's chunk
        const int q   = (d >> 1) & 3;
        float2 g = gpk[d][lane];         // one LDS.64 per d (shared by 4 pts)
#pragma unroll
        for (int p = 0; p < PPW; p++) {
            unsigned u = __shfl_sync(0xffffffffu, *(unsigned*)&m[p][q], src);
            __half2 mh = *(__half2*)&u;
            float md = (d & 1) ? __high2float(mh) : __low2float(mh);
            y0[p] += md * g.x;
            y1[p] += md * g.y;
        }
    }

#pragma unroll
    for (int p = 0; p < PPW; p++) {
        float* o = out + (size_t)(point0 + p) * DOUT;
        o[lane]      = fmaxf(y0[p], 0.f);
        o[lane + 32] = fmaxf(y1[p], 0.f);
    }
}

// ---------------------------------------------------------------------------
extern "C" void kernel_launch(void* const* d_in, const int* in_sizes, int n_in,
                              void* d_out, int out_size)
{
    const float* X     = (const float*)d_in[0];
    const float* F     = (const float*)d_in[1];
    const int*   Nbr   = (const int*)  d_in[2];
    const float* H     = (const float*)d_in[3];
    const float* gamma = (const float*)d_in[4];
    const float* gbias = (const float*)d_in[5];
    float*       out   = (float*)d_out;

    (void)in_sizes; (void)n_in; (void)out_size;

    compute_q_kernel<<<NPTS / 32, 256>>>(X, F, H);
    gather_max_gamma_kernel<<<NPTS / (WPB * PPW), WPB * 32>>>(Nbr, gamma, gbias, out);
}

// round 4
// speedup vs baseline: 3.1803x; 1.4571x over previous
#include <cuda_runtime.h>
#include <cuda_fp16.h>

#define KB    4
#define RPTS  16384
#define KAPPA 32
#define NX    3
#define NF    13
#define NIN   16
#define DOUT  64
#define NPTS  (KB * RPTS)   // 65536
#define PPW   4             // points per warp in phase 2

// 8 MB fp16 scratch: Q[point][64] halves; one 128B line per row (uint4 x 8).
__device__ uint4 g_Q4[(size_t)NPTS * 8];

// Monotonic grid-barrier counter. Never reset: each launch of B blocks adds
// exactly B, so target = old - old%B + B is correct on every graph replay.
__device__ unsigned g_count = 0;

__device__ __forceinline__ void grid_barrier() {
    __threadfence();                       // release my stores to L2 (all threads)
    __syncthreads();
    if (threadIdx.x == 0) {
        unsigned old = atomicAdd(&g_count, 1u);
        unsigned target = old - (old % gridDim.x) + gridDim.x;
        while ((int)(*(volatile unsigned*)&g_count - target) < 0) { }
        __threadfence();                   // acquire: invalidate L1D (CCTL.IVALL)
    }
    __syncthreads();
}

// ---------------------------------------------------------------------------
// Fused persistent kernel.
// Phase 1: Q = P @ H^T -> fp16 g_Q4 (grid-strided over 32-point tiles).
// Barrier.
// Phase 2: gather 32 Q rows/point, half2 running max (init 0 == fused relu),
//          butterfly reduce, Y = relu(M @ gamma + bias).
// ---------------------------------------------------------------------------
__global__ void __launch_bounds__(256) fused_kernel(
    const float* __restrict__ X,      // [NPTS, 3]
    const float* __restrict__ F,      // [NPTS, 13]
    const int*   __restrict__ Nbr,    // [NPTS, 32]
    const float* __restrict__ H,      // [64, 16]
    const float* __restrict__ gamma,  // [64, 64]
    const float* __restrict__ gbias,  // [64]
    float*       __restrict__ out)    // [NPTS, 64]
{
    __shared__ float  Psh[32][17];    // 32 points x 16 feats (padded)
    __shared__ float  Ht[NIN][DOUT];  // Ht[j][d] = H[d][j]
    __shared__ float2 gpk[DOUT][32];  // gpk[d][e] = (gamma[d][e], gamma[d][e+32])

    const int tid = threadIdx.x;

    // ---- one-time staging: H transpose + packed gamma ----
    for (int i = tid; i < NIN * DOUT; i += 256) {
        int d = i & 63, j = i >> 6;
        Ht[j][d] = H[d * NIN + j];
    }
    for (int i = tid; i < DOUT * 32; i += 256) {
        int d = i >> 5, e = i & 31;
        gpk[d][e] = make_float2(gamma[d * DOUT + e], gamma[d * DOUT + e + 32]);
    }
    __syncthreads();

    // ================= Phase 1: Q compute =================
    for (int tile = blockIdx.x; tile < NPTS / 32; tile += gridDim.x) {
        const int base = tile * 32;

        __syncthreads();   // previous iteration's Psh reads complete
        if (tid < 96) {
            Psh[tid / 3][tid % 3] = X[(size_t)base * NX + tid];
        }
        for (int i = tid; i < 32 * NF; i += 256) {
            Psh[i / NF][NX + i % NF] = F[(size_t)base * NF + i];
        }
        __syncthreads();

        const int p  = tid >> 3;      // local point 0..31
        const int c  = tid & 7;       // output chunk: d = 8c..8c+7
        const int d0 = c * 8;

        float acc[8] = {0.f, 0.f, 0.f, 0.f, 0.f, 0.f, 0.f, 0.f};
#pragma unroll
        for (int j = 0; j < NIN; j++) {
            float pj = Psh[p][j];
            float4 h0 = *(const float4*)&Ht[j][d0];
            float4 h1 = *(const float4*)&Ht[j][d0 + 4];
            acc[0] += pj * h0.x; acc[1] += pj * h0.y;
            acc[2] += pj * h0.z; acc[3] += pj * h0.w;
            acc[4] += pj * h1.x; acc[5] += pj * h1.y;
            acc[6] += pj * h1.z; acc[7] += pj * h1.w;
        }

        __half2 h01 = __floats2half2_rn(acc[0], acc[1]);
        __half2 h23 = __floats2half2_rn(acc[2], acc[3]);
        __half2 h45 = __floats2half2_rn(acc[4], acc[5]);
        __half2 h67 = __floats2half2_rn(acc[6], acc[7]);
        uint4 v;
        v.x = *(unsigned*)&h01; v.y = *(unsigned*)&h23;
        v.z = *(unsigned*)&h45; v.w = *(unsigned*)&h67;
        g_Q4[(size_t)(base + p) * 8 + c] = v;
    }

    // ================= grid barrier =================
    grid_barrier();

    // ================= Phase 2: gather + max + gamma =================
    const int warp  = tid >> 5;
    const int lane  = tid & 31;
    const int chunk = lane & 7;    // 16B chunk of row: d = 8*chunk..8*chunk+7
    const int rsel  = lane >> 3;   // which of 4 rows per LDG this lane fetches
    const int nwarps = gridDim.x * 8;

    const float b0 = gbias[lane];
    const float b1 = gbias[lane + 32];
    const __half2 zero = __float2half2_rn(0.f);

    for (int wt = blockIdx.x * 8 + warp; wt < NPTS / PPW; wt += nwarps) {
        const int point0 = wt * PPW;
        const int k      = point0 >> 14;               // R = 16384

        int my_idx[PPW];
#pragma unroll
        for (int p = 0; p < PPW; p++)
            my_idx[p] = Nbr[(size_t)(point0 + p) * KAPPA + lane];

        const uint4* __restrict__ Qk = g_Q4 + (size_t)k * RPTS * 8;

        __half2 m[PPW][4];
#pragma unroll
        for (int p = 0; p < PPW; p++) {
            m[p][0] = zero; m[p][1] = zero; m[p][2] = zero; m[p][3] = zero;
        }

#pragma unroll
        for (int p = 0; p < PPW; p++) {
#pragma unroll
            for (int i = 0; i < KAPPA / 4; i++) {      // 8 LDG.128, 4 rows each
                int idx = __shfl_sync(0xffffffffu, my_idx[p], 4 * i + rsel);
                uint4 v = Qk[(size_t)idx * 8 + chunk];
                m[p][0] = __hmax2(m[p][0], *(__half2*)&v.x);
                m[p][1] = __hmax2(m[p][1], *(__half2*)&v.y);
                m[p][2] = __hmax2(m[p][2], *(__half2*)&v.z);
                m[p][3] = __hmax2(m[p][3], *(__half2*)&v.w);
            }
        }

        // reduce the 4 rsel partials (lanes differing in bits 3,4)
#pragma unroll
        for (int off = 8; off < 32; off <<= 1) {
#pragma unroll
            for (int p = 0; p < PPW; p++) {
#pragma unroll
                for (int q = 0; q < 4; q++) {
                    unsigned u = __shfl_xor_sync(0xffffffffu, *(unsigned*)&m[p][q], off);
                    m[p][q] = __hmax2(m[p][q], *(__half2*)&u);
                }
            }
        }

        // gamma matvec: Y[e] = relu( sum_d M[d]*gamma[d][e] + bias[e] )
        float y0[PPW], y1[PPW];
#pragma unroll
        for (int p = 0; p < PPW; p++) { y0[p] = b0; y1[p] = b1; }

#pragma unroll
        for (int d = 0; d < DOUT; d++) {
            const int src = d >> 3;
            const int q   = (d >> 1) & 3;
            float2 g = gpk[d][lane];
#pragma unroll
            for (int p = 0; p < PPW; p++) {
                unsigned u = __shfl_sync(0xffffffffu, *(unsigned*)&m[p][q], src);
                __half2 mh = *(__half2*)&u;
                float md = (d & 1) ? __high2float(mh) : __low2float(mh);
                y0[p] += md * g.x;
                y1[p] += md * g.y;
            }
        }

#pragma unroll
        for (int p = 0; p < PPW; p++) {
            float* o = out + (size_t)(point0 + p) * DOUT;
            o[lane]      = fmaxf(y0[p], 0.f);
            o[lane + 32] = fmaxf(y1[p], 0.f);
        }
    }
}

// ---------------------------------------------------------------------------
extern "C" void kernel_launch(void* const* d_in, const int* in_sizes, int n_in,
                              void* d_out, int out_size)
{
    const float* X     = (const float*)d_in[0];
    const float* F     = (const float*)d_in[1];
    const int*   Nbr   = (const int*)  d_in[2];
    const float* H     = (const float*)d_in[3];
    const float* gamma = (const float*)d_in[4];
    const float* gbias = (const float*)d_in[5];
    float*       out   = (float*)d_out;

    (void)in_sizes; (void)n_in; (void)out_size;

    // Guaranteed-co-resident persistent launch: SMs * achievable blocks/SM.
    int dev = 0, sms = 148, maxb = 1;
    cudaGetDevice(&dev);
    cudaDeviceGetAttribute(&sms, cudaDevAttrMultiProcessorCount, dev);
    cudaOccupancyMaxActiveBlocksPerMultiprocessor(&maxb, fused_kernel, 256, 0);
    if (maxb < 1) maxb = 1;
    if (maxb > 8) maxb = 8;
    int blocks = sms * maxb;

    fused_kernel<<<blocks, 256>>>(X, F, Nbr, H, gamma, gbias, out);
}

// round 5
// speedup vs baseline: 3.5179x; 1.1061x over previous
#include <cuda_runtime.h>
#include <cuda_fp16.h>

#define KB    4
#define RPTS  16384
#define KAPPA 32
#define NX    3
#define NF    13
#define NIN   16
#define DOUT  64
#define NPTS  (KB * RPTS)   // 65536
#define PPW   4             // points per warp in phase 2

// 8 MB fp16 scratch: Q[point][64] halves; one 128B line per row (uint4 x 8).
__device__ uint4 g_Q4[(size_t)NPTS * 8];

// Monotonic grid-barrier counter (never reset; replay-safe).
__device__ unsigned g_count = 0;

__device__ __forceinline__ void grid_barrier() {
    __threadfence();
    __syncthreads();
    if (threadIdx.x == 0) {
        unsigned old = atomicAdd(&g_count, 1u);
        unsigned target = old - (old % gridDim.x) + gridDim.x;
        while ((int)(*(volatile unsigned*)&g_count - target) < 0) { }
        __threadfence();
    }
    __syncthreads();
}

// ---------------------------------------------------------------------------
// Fused persistent kernel.
// Phase 1: Q = P @ H^T -> fp16 g_Q4.   Barrier.
// Phase 2: gather 32 Q rows/point, half2 running max (init 0 == fused relu),
//          butterfly reduce, m -> shared (STS.128), then
//          Y = relu(M @ gamma + bias) with fp16 gamma (fp32 accumulate) and
//          broadcast LDS.128 reads of m (no shuffles in the matvec).
// ---------------------------------------------------------------------------
__global__ void __launch_bounds__(256) fused_kernel(
    const float* __restrict__ X,      // [NPTS, 3]
    const float* __restrict__ F,      // [NPTS, 13]
    const int*   __restrict__ Nbr,    // [NPTS, 32]
    const float* __restrict__ H,      // [64, 16]
    const float* __restrict__ gamma,  // [64, 64]
    const float* __restrict__ gbias,  // [64]
    float*       __restrict__ out)    // [NPTS, 64]
{
    __shared__ float   Psh[32][17];     // phase-1 staging
    __shared__ float   Ht[NIN][DOUT];   // Ht[j][d] = H[d][j]
    __shared__ __half2 gsh[DOUT][32];   // gsh[d][e] = (gamma[d][e], gamma[d][e+32]) fp16
    __shared__ uint4   m_sh[8][PPW][8]; // per-warp per-point 64 halves (d-order)

    const int tid = threadIdx.x;

    // ---- one-time staging ----
    for (int i = tid; i < NIN * DOUT; i += 256) {
        int d = i & 63, j = i >> 6;
        Ht[j][d] = H[d * NIN + j];
    }
    for (int i = tid; i < DOUT * 32; i += 256) {
        int d = i >> 5, e = i & 31;
        gsh[d][e] = __floats2half2_rn(gamma[d * DOUT + e], gamma[d * DOUT + e + 32]);
    }
    __syncthreads();

    // ================= Phase 1: Q compute =================
    for (int tile = blockIdx.x; tile < NPTS / 32; tile += gridDim.x) {
        const int base = tile * 32;

        __syncthreads();
        if (tid < 96) {
            Psh[tid / 3][tid % 3] = X[(size_t)base * NX + tid];
        }
        for (int i = tid; i < 32 * NF; i += 256) {
            Psh[i / NF][NX + i % NF] = F[(size_t)base * NF + i];
        }
        __syncthreads();

        const int p  = tid >> 3;
        const int c  = tid & 7;
        const int d0 = c * 8;

        float acc[8] = {0.f, 0.f, 0.f, 0.f, 0.f, 0.f, 0.f, 0.f};
#pragma unroll
        for (int j = 0; j < NIN; j++) {
            float pj = Psh[p][j];
            float4 h0 = *(const float4*)&Ht[j][d0];
            float4 h1 = *(const float4*)&Ht[j][d0 + 4];
            acc[0] += pj * h0.x; acc[1] += pj * h0.y;
            acc[2] += pj * h0.z; acc[3] += pj * h0.w;
            acc[4] += pj * h1.x; acc[5] += pj * h1.y;
            acc[6] += pj * h1.z; acc[7] += pj * h1.w;
        }

        __half2 h01 = __floats2half2_rn(acc[0], acc[1]);
        __half2 h23 = __floats2half2_rn(acc[2], acc[3]);
        __half2 h45 = __floats2half2_rn(acc[4], acc[5]);
        __half2 h67 = __floats2half2_rn(acc[6], acc[7]);
        uint4 v;
        v.x = *(unsigned*)&h01; v.y = *(unsigned*)&h23;
        v.z = *(unsigned*)&h45; v.w = *(unsigned*)&h67;
        g_Q4[(size_t)(base + p) * 8 + c] = v;
    }

    // ================= grid barrier =================
    grid_barrier();

    // ================= Phase 2 =================
    const int warp  = tid >> 5;
    const int lane  = tid & 31;
    const int chunk = lane & 7;    // 16B chunk of row: d = 8*chunk..8*chunk+7
    const int rsel  = lane >> 3;
    const int nwarps = gridDim.x * 8;

    const float b0 = gbias[lane];
    const float b1 = gbias[lane + 32];
    const __half2 zero = __float2half2_rn(0.f);

    for (int wt = blockIdx.x * 8 + warp; wt < NPTS / PPW; wt += nwarps) {
        const int point0 = wt * PPW;
        const int k      = point0 >> 14;               // R = 16384

        int my_idx[PPW];
#pragma unroll
        for (int p = 0; p < PPW; p++)
            my_idx[p] = Nbr[(size_t)(point0 + p) * KAPPA + lane];

        const uint4* __restrict__ Qk = g_Q4 + (size_t)k * RPTS * 8;

        __half2 m[PPW][4];
#pragma unroll
        for (int p = 0; p < PPW; p++) {
            m[p][0] = zero; m[p][1] = zero; m[p][2] = zero; m[p][3] = zero;
        }

#pragma unroll
        for (int p = 0; p < PPW; p++) {
#pragma unroll
            for (int i = 0; i < KAPPA / 4; i++) {      // 8 LDG.128, 4 rows each
                int idx = __shfl_sync(0xffffffffu, my_idx[p], 4 * i + rsel);
                uint4 v = Qk[(size_t)idx * 8 + chunk];
                m[p][0] = __hmax2(m[p][0], *(__half2*)&v.x);
                m[p][1] = __hmax2(m[p][1], *(__half2*)&v.y);
                m[p][2] = __hmax2(m[p][2], *(__half2*)&v.z);
                m[p][3] = __hmax2(m[p][3], *(__half2*)&v.w);
            }
        }

        // reduce the 4 rsel partials (lanes differing in bits 3,4)
#pragma unroll
        for (int off = 8; off < 32; off <<= 1) {
#pragma unroll
            for (int p = 0; p < PPW; p++) {
#pragma unroll
                for (int q = 0; q < 4; q++) {
                    unsigned u = __shfl_xor_sync(0xffffffffu, *(unsigned*)&m[p][q], off);
                    m[p][q] = __hmax2(m[p][q], *(__half2*)&u);
                }
            }
        }

        // lanes 0..7 publish their chunk (8 halves, d-ordered) per point
        if (lane < 8) {
#pragma unroll
            for (int p = 0; p < PPW; p++) {
                uint4 mv;
                mv.x = *(unsigned*)&m[p][0];
                mv.y = *(unsigned*)&m[p][1];
                mv.z = *(unsigned*)&m[p][2];
                mv.w = *(unsigned*)&m[p][3];
                m_sh[warp][p][lane] = mv;   // STS.128, 8 lanes -> 1 wavefront
            }
        }
        __syncwarp();

        // --- gamma matvec: Y[e] = relu( sum_d M[d]*gamma[d][e] + bias[e] ) ---
        float y0[PPW], y1[PPW];
#pragma unroll
        for (int p = 0; p < PPW; p++) { y0[p] = b0; y1[p] = b1; }

#pragma unroll
        for (int dg = 0; dg < 8; dg++) {
            uint4 mv0 = m_sh[warp][0][dg];   // broadcast LDS.128 (8 halves)
            uint4 mv1 = m_sh[warp][1][dg];
            uint4 mv2 = m_sh[warp][2][dg];
            uint4 mv3 = m_sh[warp][3][dg];
#pragma unroll
            for (int jp = 0; jp < 4; jp++) {        // pairs of d
                const int d = dg * 8 + jp * 2;
                float2 g0 = __half22float2(gsh[d][lane]);       // 1 wf
                float2 g1 = __half22float2(gsh[d + 1][lane]);   // 1 wf
                float2 f;
                f = __half22float2(((const __half2*)&mv0)[jp]);
                y0[0] += f.x * g0.x; y1[0] += f.x * g0.y;
                y0[0] += f.y * g1.x; y1[0] += f.y * g1.y;
                f = __half22float2(((const __half2*)&mv1)[jp]);
                y0[1] += f.x * g0.x; y1[1] += f.x * g0.y;
                y0[1] += f.y * g1.x; y1[1] += f.y * g1.y;
                f = __half22float2(((const __half2*)&mv2)[jp]);
                y0[2] += f.x * g0.x; y1[2] += f.x * g0.y;
                y0[2] += f.y * g1.x; y1[2] += f.y * g1.y;
                f = __half22float2(((const __half2*)&mv3)[jp]);
                y0[3] += f.x * g0.x; y1[3] += f.x * g0.y;
                y0[3] += f.y * g1.x; y1[3] += f.y * g1.y;
            }
        }

#pragma unroll
        for (int p = 0; p < PPW; p++) {
            float* o = out + (size_t)(point0 + p) * DOUT;
            o[lane]      = fmaxf(y0[p], 0.f);
            o[lane + 32] = fmaxf(y1[p], 0.f);
        }
    }
}

// ---------------------------------------------------------------------------
extern "C" void kernel_launch(void* const* d_in, const int* in_sizes, int n_in,
                              void* d_out, int out_size)
{
    const float* X     = (const float*)d_in[0];
    const float* F     = (const float*)d_in[1];
    const int*   Nbr   = (const int*)  d_in[2];
    const float* H     = (const float*)d_in[3];
    const float* gamma = (const float*)d_in[4];
    const float* gbias = (const float*)d_in[5];
    float*       out   = (float*)d_out;

    (void)in_sizes; (void)n_in; (void)out_size;

    int dev = 0, sms = 148, maxb = 1;
    cudaGetDevice(&dev);
    cudaDeviceGetAttribute(&sms, cudaDevAttrMultiProcessorCount, dev);
    cudaOccupancyMaxActiveBlocksPerMultiprocessor(&maxb, fused_kernel, 256, 0);
    if (maxb < 1) maxb = 1;
    if (maxb > 8) maxb = 8;
    int blocks = sms * maxb;

    fused_kernel<<<blocks, 256>>>(X, F, Nbr, H, gamma, gbias, out);
}

// round 8
// speedup vs baseline: 3.8799x; 1.1029x over previous
#include <cuda_runtime.h>
#include <cuda_fp16.h>

#define KB    4
#define RPTS  16384
#define KAPPA 32
#define NX    3
#define NF    13
#define NIN   16
#define DOUT  64
#define NPTS  (KB * RPTS)   // 65536
#define MS    72            // padded halves per m_sh row (144B: conflict-free ldmatrix)
#define GS    72            // padded halves per gamma row

// 8 MB fp16 scratch: Q[point][64] halves; one 128B line per row (uint4 x 8).
__device__ uint4 g_Q4[(size_t)NPTS * 8];

// Monotonic grid-barrier counter (never reset; replay-safe).
__device__ unsigned g_count = 0;

__device__ __forceinline__ void grid_barrier() {
    __threadfence();
    __syncthreads();
    if (threadIdx.x == 0) {
        unsigned old = atomicAdd(&g_count, 1u);
        unsigned target = old - (old % gridDim.x) + gridDim.x;
        while ((int)(*(volatile unsigned*)&g_count - target) < 0) { }
        __threadfence();
    }
    __syncthreads();
}

__device__ __forceinline__ unsigned smem_u32(const void* p) {
    return (unsigned)__cvta_generic_to_shared(p);
}

#define LDMATRIX_X4(r0, r1, r2, r3, addr)                                   \
    asm volatile("ldmatrix.sync.aligned.m8n8.x4.shared.b16 {%0,%1,%2,%3}, [%4];" \
        : "=r"(r0), "=r"(r1), "=r"(r2), "=r"(r3) : "r"(addr))

#define LDMATRIX_X4_T(r0, r1, r2, r3, addr)                                 \
    asm volatile("ldmatrix.sync.aligned.m8n8.x4.trans.shared.b16 {%0,%1,%2,%3}, [%4];" \
        : "=r"(r0), "=r"(r1), "=r"(r2), "=r"(r3) : "r"(addr))

#define MMA_16816(c, a0, a1, a2, a3, b0, b1)                                \
    asm volatile("mma.sync.aligned.m16n8k16.row.col.f32.f16.f16.f32 "       \
        "{%0,%1,%2,%3}, {%4,%5,%6,%7}, {%8,%9}, {%0,%1,%2,%3};"             \
        : "+f"((c)[0]), "+f"((c)[1]), "+f"((c)[2]), "+f"((c)[3])            \
        : "r"(a0), "r"(a1), "r"(a2), "r"(a3), "r"(b0), "r"(b1))

// ---------------------------------------------------------------------------
// Fused persistent kernel.
// Phase 1: Q = P @ H^T -> fp16 g_Q4.   Grid barrier.
// Phase 2: per warp, 16 points: 4x(gather 4 points, half2 max, butterfly
//          reduce, park maxima fp16 in shared), then one m16n64k64 HMMA
//          GEMM against fp16 gamma (fp32 accumulate), bias + relu, store.
// ---------------------------------------------------------------------------
__global__ void __launch_bounds__(256, 4) fused_kernel(
    const float* __restrict__ X,      // [NPTS, 3]
    const float* __restrict__ F,      // [NPTS, 13]
    const int*   __restrict__ Nbr,    // [NPTS, 32]
    const float* __restrict__ H,      // [64, 16]
    const float* __restrict__ gamma,  // [64, 64]
    const float* __restrict__ gbias,  // [64]
    float*       __restrict__ out)    // [NPTS, 64]
{
    __shared__ float  Psh[32][17];                      // phase-1 staging
    __shared__ float  Ht[NIN][DOUT];                    // Ht[j][d] = H[d][j]
    __shared__ __align__(16) __half gsh[DOUT][GS];      // fp16 gamma, padded rows
    __shared__ __align__(16) __half m_sh[8][16][MS];    // per-warp 16x64 maxima
    __shared__ float  bias_sh[DOUT];

    const int tid = threadIdx.x;

    // ---- one-time staging ----
    for (int i = tid; i < NIN * DOUT; i += 256) {
        int d = i & 63, j = i >> 6;
        Ht[j][d] = H[d * NIN + j];
    }
    for (int i = tid; i < DOUT * DOUT; i += 256) {
        int d = i >> 6, e = i & 63;
        gsh[d][e] = __float2half_rn(gamma[d * DOUT + e]);
    }
    if (tid < DOUT) bias_sh[tid] = gbias[tid];
    __syncthreads();

    // ================= Phase 1: Q compute =================
    for (int tile = blockIdx.x; tile < NPTS / 32; tile += gridDim.x) {
        const int base = tile * 32;

        __syncthreads();
        if (tid < 96) {
            Psh[tid / 3][tid % 3] = X[(size_t)base * NX + tid];
        }
        for (int i = tid; i < 32 * NF; i += 256) {
            Psh[i / NF][NX + i % NF] = F[(size_t)base * NF + i];
        }
        __syncthreads();

        const int p  = tid >> 3;
        const int c  = tid & 7;
        const int d0 = c * 8;

        float acc[8] = {0.f, 0.f, 0.f, 0.f, 0.f, 0.f, 0.f, 0.f};
#pragma unroll
        for (int j = 0; j < NIN; j++) {
            float pj = Psh[p][j];
            float4 h0 = *(const float4*)&Ht[j][d0];
            float4 h1 = *(const float4*)&Ht[j][d0 + 4];
            acc[0] += pj * h0.x; acc[1] += pj * h0.y;
            acc[2] += pj * h0.z; acc[3] += pj * h0.w;
            acc[4] += pj * h1.x; acc[5] += pj * h1.y;
            acc[6] += pj * h1.z; acc[7] += pj * h1.w;
        }

        __half2 h01 = __floats2half2_rn(acc[0], acc[1]);
        __half2 h23 = __floats2half2_rn(acc[2], acc[3]);
        __half2 h45 = __floats2half2_rn(acc[4], acc[5]);
        __half2 h67 = __floats2half2_rn(acc[6], acc[7]);
        uint4 v;
        v.x = *(unsigned*)&h01; v.y = *(unsigned*)&h23;
        v.z = *(unsigned*)&h45; v.w = *(unsigned*)&h67;
        g_Q4[(size_t)(base + p) * 8 + c] = v;
    }

    // ================= grid barrier =================
    grid_barrier();

    // ================= Phase 2 =================
    const int warp  = tid >> 5;
    const int lane  = tid & 31;
    const int chunk = lane & 7;
    const int rsel  = lane >> 3;
    const int nwarps = gridDim.x * 8;
    const __half2 zero = __float2half2_rn(0.f);

    // ldmatrix lane->address components (constant per thread)
    const int mrow  = lane & 15;          // A: row within 16
    const int mkoff = (lane >> 4) << 3;   // A: +8 k for upper half-warp
    // B uses the same lane&15 / (lane>>4)*8 split (k-row / +8 n)

    for (int wt = blockIdx.x * 8 + warp; wt < NPTS / 16; wt += nwarps) {
        const int point0 = wt * 16;
        const int k      = point0 >> 14;               // R = 16384
        const uint4* __restrict__ Qk = g_Q4 + (size_t)k * RPTS * 8;

        // ---- 4 sub-batches of 4 points: gather + max + reduce + park ----
#pragma unroll
        for (int sub = 0; sub < 4; sub++) {
            const int p0 = point0 + sub * 4;

            int my_idx[4];
#pragma unroll
            for (int p = 0; p < 4; p++)
                my_idx[p] = Nbr[(size_t)(p0 + p) * KAPPA + lane];

            __half2 m[4][4];
#pragma unroll
            for (int p = 0; p < 4; p++) {
                m[p][0] = zero; m[p][1] = zero; m[p][2] = zero; m[p][3] = zero;
            }

#pragma unroll
            for (int p = 0; p < 4; p++) {
#pragma unroll
                for (int i = 0; i < KAPPA / 4; i++) {   // 8 LDG.128, 4 rows each
                    int idx = __shfl_sync(0xffffffffu, my_idx[p], 4 * i + rsel);
                    uint4 v = Qk[(size_t)idx * 8 + chunk];
                    m[p][0] = __hmax2(m[p][0], *(__half2*)&v.x);
                    m[p][1] = __hmax2(m[p][1], *(__half2*)&v.y);
                    m[p][2] = __hmax2(m[p][2], *(__half2*)&v.z);
                    m[p][3] = __hmax2(m[p][3], *(__half2*)&v.w);
                }
            }

#pragma unroll
            for (int off = 8; off < 32; off <<= 1) {
#pragma unroll
                for (int p = 0; p < 4; p++) {
#pragma unroll
                    for (int q = 0; q < 4; q++) {
                        unsigned u = __shfl_xor_sync(0xffffffffu, *(unsigned*)&m[p][q], off);
                        m[p][q] = __hmax2(m[p][q], *(__half2*)&u);
                    }
                }
            }

            if (lane < 8) {                 // lane == chunk: d = 8*lane..8*lane+7
#pragma unroll
                for (int p = 0; p < 4; p++) {
                    uint4 mv;
                    mv.x = *(unsigned*)&m[p][0];
                    mv.y = *(unsigned*)&m[p][1];
                    mv.z = *(unsigned*)&m[p][2];
                    mv.w = *(unsigned*)&m[p][3];
                    *(uint4*)&m_sh[warp][sub * 4 + p][lane * 8] = mv;
                }
            }
        }
        __syncwarp();

        // ---- HMMA matvec: [16 x 64] = [16 x 64] @ gamma[64 x 64] ----
        const int r0 = lane >> 2;          // C row (and +8)
        const int cc = (lane & 3) * 2;     // C col pair within n-frag

#pragma unroll
        for (int nh = 0; nh < 2; nh++) {   // two halves of 4 n-frags
            float c[4][4];
#pragma unroll
            for (int f = 0; f < 4; f++) {
                float2 bb = *(const float2*)&bias_sh[(nh * 4 + f) * 8 + cc];
                c[f][0] = bb.x; c[f][1] = bb.y;   // row r0
                c[f][2] = bb.x; c[f][3] = bb.y;   // row r0+8
            }

#pragma unroll
            for (int kf = 0; kf < 4; kf++) {
                unsigned a0, a1, a2, a3;
                unsigned aaddr = smem_u32(&m_sh[warp][mrow][kf * 16 + mkoff]);
                LDMATRIX_X4(a0, a1, a2, a3, aaddr);

#pragma unroll
                for (int fq = 0; fq < 2; fq++) {
                    const int n0 = (nh * 4 + fq * 2) * 8;
                    unsigned b0, b1, b2, b3;
                    unsigned baddr = smem_u32(&gsh[kf * 16 + mrow][n0 + mkoff]);
                    LDMATRIX_X4_T(b0, b1, b2, b3, baddr);
                    MMA_16816(c[fq * 2],     a0, a1, a2, a3, b0, b1);
                    MMA_16816(c[fq * 2 + 1], a0, a1, a2, a3, b2, b3);
                }
            }

            // relu + store
#pragma unroll
            for (int f = 0; f < 4; f++) {
                const int n0 = (nh * 4 + f) * 8;
                float2 v0 = make_float2(fmaxf(c[f][0], 0.f), fmaxf(c[f][1], 0.f));
                float2 v1 = make_float2(fmaxf(c[f][2], 0.f), fmaxf(c[f][3], 0.f));
                *(float2*)&out[(size_t)(point0 + r0)     * DOUT + n0 + cc] = v0;
                *(float2*)&out[(size_t)(point0 + r0 + 8) * DOUT + n0 + cc] = v1;
            }
        }
    }
}

// ---------------------------------------------------------------------------
extern "C" void kernel_launch(void* const* d_in, const int* in_sizes, int n_in,
                              void* d_out, int out_size)
{
    const float* X     = (const float*)d_in[0];
    const float* F     = (const float*)d_in[1];
    const int*   Nbr   = (const int*)  d_in[2];
    const float* H     = (const float*)d_in[3];
    const float* gamma = (const float*)d_in[4];
    const float* gbias = (const float*)d_in[5];
    float*       out   = (float*)d_out;

    (void)in_sizes; (void)n_in; (void)out_size;

    int dev = 0, sms = 148, maxb = 1;
    cudaGetDevice(&dev);
    cudaDeviceGetAttribute(&sms, cudaDevAttrMultiProcessorCount, dev);
    cudaOccupancyMaxActiveBlocksPerMultiprocessor(&maxb, fused_kernel, 256, 0);
    if (maxb < 1) maxb = 1;
    if (maxb > 8) maxb = 8;
    int blocks = sms * maxb;

    fused_kernel<<<blocks, 256>>>(X, F, Nbr, H, gamma, gbias, out);
}

// round 9
// speedup vs baseline: 4.2319x; 1.0907x over previous
#include <cuda_runtime.h>
#include <cuda_fp16.h>

#define KB    4
#define RPTS  16384
#define KAPPA 32
#define NX    3
#define NF    13
#define NIN   16
#define DOUT  64
#define NPTS  (KB * RPTS)   // 65536
#define MS    72            // padded halves per m_sh row (144B: conflict-free ldmatrix)
#define GS    72            // padded halves per gamma row
#define IS    36            // padded ints per idx_sh row

// 8 MB fp16 scratch: Q[point][64] halves; one 128B line per row (uint4 x 8).
__device__ uint4 g_Q4[(size_t)NPTS * 8];

// Monotonic grid-barrier counter (never reset; replay-safe).
__device__ unsigned g_count = 0;

__device__ __forceinline__ void grid_barrier() {
    __threadfence();
    __syncthreads();
    if (threadIdx.x == 0) {
        unsigned old = atomicAdd(&g_count, 1u);
        unsigned target = old - (old % gridDim.x) + gridDim.x;
        while ((int)(*(volatile unsigned*)&g_count - target) < 0) { }
        __threadfence();
    }
    __syncthreads();
}

__device__ __forceinline__ unsigned smem_u32(const void* p) {
    return (unsigned)__cvta_generic_to_shared(p);
}

#define LDMATRIX_X4(r0, r1, r2, r3, addr)                                   \
    asm volatile("ldmatrix.sync.aligned.m8n8.x4.shared.b16 {%0,%1,%2,%3}, [%4];" \
        : "=r"(r0), "=r"(r1), "=r"(r2), "=r"(r3) : "r"(addr))

#define LDMATRIX_X4_T(r0, r1, r2, r3, addr)                                 \
    asm volatile("ldmatrix.sync.aligned.m8n8.x4.trans.shared.b16 {%0,%1,%2,%3}, [%4];" \
        : "=r"(r0), "=r"(r1), "=r"(r2), "=r"(r3) : "r"(addr))

#define MMA_16816(c, a0, a1, a2, a3, b0, b1)                                \
    asm volatile("mma.sync.aligned.m16n8k16.row.col.f32.f16.f16.f32 "       \
        "{%0,%1,%2,%3}, {%4,%5,%6,%7}, {%8,%9}, {%0,%1,%2,%3};"             \
        : "+f"((c)[0]), "+f"((c)[1]), "+f"((c)[2]), "+f"((c)[3])            \
        : "r"(a0), "r"(a1), "r"(a2), "r"(a3), "r"(b0), "r"(b1))

// ---------------------------------------------------------------------------
// Fused persistent kernel.
// Phase 1: Q = P @ H^T -> fp16 g_Q4.   Grid barrier.
// Phase 2: per warp, 16 points in 4 sub-batches of 4. Within a sub-batch the
//   8-lane group rsel owns point (sub*4 + rsel) entirely: it walks all 32 of
//   that point's neighbors (indices via shared, no shuffles), keeps a complete
//   running max in registers (init 0 == fused relu), and parks it with one
//   warp-wide STS.128. Then one m16n64k64 HMMA GEMM vs fp16 gamma (fp32
//   accumulate), bias + relu, store.
// ---------------------------------------------------------------------------
__global__ void __launch_bounds__(256, 4) fused_kernel(
    const float* __restrict__ X,      // [NPTS, 3]
    const float* __restrict__ F,      // [NPTS, 13]
    const int*   __restrict__ Nbr,    // [NPTS, 32]
    const float* __restrict__ H,      // [64, 16]
    const float* __restrict__ gamma,  // [64, 64]
    const float* __restrict__ gbias,  // [64]
    float*       __restrict__ out)    // [NPTS, 64]
{
    __shared__ float  Psh[32][17];                      // phase-1 staging
    __shared__ float  Ht[NIN][DOUT];                    // Ht[j][d] = H[d][j]
    __shared__ __align__(16) __half gsh[DOUT][GS];      // fp16 gamma, padded rows
    __shared__ __align__(16) __half m_sh[8][16][MS];    // per-warp 16x64 maxima
    __shared__ __align__(16) int    idx_sh[8][4][IS];   // per-warp 4x32 indices
    __shared__ float  bias_sh[DOUT];

    const int tid = threadIdx.x;

    // ---- one-time staging ----
    for (int i = tid; i < NIN * DOUT; i += 256) {
        int d = i & 63, j = i >> 6;
        Ht[j][d] = H[d * NIN + j];
    }
    for (int i = tid; i < DOUT * DOUT; i += 256) {
        int d = i >> 6, e = i & 63;
        gsh[d][e] = __float2half_rn(gamma[d * DOUT + e]);
    }
    if (tid < DOUT) bias_sh[tid] = gbias[tid];
    __syncthreads();

    // ================= Phase 1: Q compute =================
    for (int tile = blockIdx.x; tile < NPTS / 32; tile += gridDim.x) {
        const int base = tile * 32;

        __syncthreads();
        if (tid < 96) {
            Psh[tid / 3][tid % 3] = X[(size_t)base * NX + tid];
        }
        for (int i = tid; i < 32 * NF; i += 256) {
            Psh[i / NF][NX + i % NF] = F[(size_t)base * NF + i];
        }
        __syncthreads();

        const int p  = tid >> 3;
        const int c  = tid & 7;
        const int d0 = c * 8;

        float acc[8] = {0.f, 0.f, 0.f, 0.f, 0.f, 0.f, 0.f, 0.f};
#pragma unroll
        for (int j = 0; j < NIN; j++) {
            float pj = Psh[p][j];
            float4 h0 = *(const float4*)&Ht[j][d0];
            float4 h1 = *(const float4*)&Ht[j][d0 + 4];
            acc[0] += pj * h0.x; acc[1] += pj * h0.y;
            acc[2] += pj * h0.z; acc[3] += pj * h0.w;
            acc[4] += pj * h1.x; acc[5] += pj * h1.y;
            acc[6] += pj * h1.z; acc[7] += pj * h1.w;
        }

        __half2 h01 = __floats2half2_rn(acc[0], acc[1]);
        __half2 h23 = __floats2half2_rn(acc[2], acc[3]);
        __half2 h45 = __floats2half2_rn(acc[4], acc[5]);
        __half2 h67 = __floats2half2_rn(acc[6], acc[7]);
        uint4 v;
        v.x = *(unsigned*)&h01; v.y = *(unsigned*)&h23;
        v.z = *(unsigned*)&h45; v.w = *(unsigned*)&h67;
        g_Q4[(size_t)(base + p) * 8 + c] = v;
    }

    // ================= grid barrier =================
    grid_barrier();

    // ================= Phase 2 =================
    const int warp  = tid >> 5;
    const int lane  = tid & 31;
    const int chunk = lane & 7;    // 16B chunk of Q row: d = 8*chunk..8*chunk+7
    const int rsel  = lane >> 3;   // which of the 4 sub-batch points this lane owns
    const int nwarps = gridDim.x * 8;
    const __half2 zero = __float2half2_rn(0.f);

    // ldmatrix lane->address components
    const int mrow  = lane & 15;
    const int mkoff = (lane >> 4) << 3;

    for (int wt = blockIdx.x * 8 + warp; wt < NPTS / 16; wt += nwarps) {
        const int point0 = wt * 16;
        const int k      = point0 >> 14;               // R = 16384
        const uint4* __restrict__ Qk = g_Q4 + (size_t)k * RPTS * 8;

        // ---- 4 sub-batches of 4 points ----
#pragma unroll
        for (int sub = 0; sub < 4; sub++) {
            __syncwarp();   // idx_sh / m_sh from previous sub|iter fully consumed

            // stage the 4x32 neighbor indices: one LDG.128 + one STS.128
            uint4 iv = ((const uint4*)(Nbr + (size_t)(point0 + sub * 4) * KAPPA))[lane];
            *(uint4*)&idx_sh[warp][lane >> 3][(lane & 7) * 4] = iv;
            __syncwarp();

            const int* __restrict__ myrow = idx_sh[warp][rsel];

            __half2 m0 = zero, m1 = zero, m2 = zero, m3 = zero;
#pragma unroll
            for (int ii = 0; ii < 8; ii++) {
                int4 iq = *(const int4*)&myrow[ii * 4];   // 4 idx, group-broadcast
                uint4 v0 = Qk[(size_t)iq.x * 8 + chunk];
                uint4 v1 = Qk[(size_t)iq.y * 8 + chunk];
                uint4 v2 = Qk[(size_t)iq.z * 8 + chunk];
                uint4 v3 = Qk[(size_t)iq.w * 8 + chunk];
                __half2 a0 = __hmax2(*(__half2*)&v0.x, *(__half2*)&v1.x);
                __half2 a1 = __hmax2(*(__half2*)&v0.y, *(__half2*)&v1.y);
                __half2 a2 = __hmax2(*(__half2*)&v0.z, *(__half2*)&v1.z);
                __half2 a3 = __hmax2(*(__half2*)&v0.w, *(__half2*)&v1.w);
                __half2 b0 = __hmax2(*(__half2*)&v2.x, *(__half2*)&v3.x);
                __half2 b1 = __hmax2(*(__half2*)&v2.y, *(__half2*)&v3.y);
                __half2 b2 = __hmax2(*(__half2*)&v2.z, *(__half2*)&v3.z);
                __half2 b3 = __hmax2(*(__half2*)&v2.w, *(__half2*)&v3.w);
                m0 = __hmax2(m0, __hmax2(a0, b0));
                m1 = __hmax2(m1, __hmax2(a1, b1));
                m2 = __hmax2(m2, __hmax2(a2, b2));
                m3 = __hmax2(m3, __hmax2(a3, b3));
            }

            // park: every lane stores its complete 16B chunk of its point
            uint4 mv;
            mv.x = *(unsigned*)&m0; mv.y = *(unsigned*)&m1;
            mv.z = *(unsigned*)&m2; mv.w = *(unsigned*)&m3;
            *(uint4*)&m_sh[warp][sub * 4 + rsel][chunk * 8] = mv;
        }
        __syncwarp();

        // ---- HMMA matvec: [16 x 64] = m_sh @ gamma[64 x 64] ----
        const int r0 = lane >> 2;
        const int cc = (lane & 3) * 2;

#pragma unroll
        for (int nh = 0; nh < 2; nh++) {
            float c[4][4];
#pragma unroll
            for (int f = 0; f < 4; f++) {
                float2 bb = *(const float2*)&bias_sh[(nh * 4 + f) * 8 + cc];
                c[f][0] = bb.x; c[f][1] = bb.y;
                c[f][2] = bb.x; c[f][3] = bb.y;
            }

#pragma unroll
            for (int kf = 0; kf < 4; kf++) {
                unsigned a0, a1, a2, a3;
                unsigned aaddr = smem_u32(&m_sh[warp][mrow][kf * 16 + mkoff]);
                LDMATRIX_X4(a0, a1, a2, a3, aaddr);

#pragma unroll
                for (int fq = 0; fq < 2; fq++) {
                    const int n0 = (nh * 4 + fq * 2) * 8;
                    unsigned b0, b1, b2, b3;
                    unsigned baddr = smem_u32(&gsh[kf * 16 + mrow][n0 + mkoff]);
                    LDMATRIX_X4_T(b0, b1, b2, b3, baddr);
                    MMA_16816(c[fq * 2],     a0, a1, a2, a3, b0, b1);
                    MMA_16816(c[fq * 2 + 1], a0, a1, a2, a3, b2, b3);
                }
            }

#pragma unroll
            for (int f = 0; f < 4; f++) {
                const int n0 = (nh * 4 + f) * 8;
                float2 v0 = make_float2(fmaxf(c[f][0], 0.f), fmaxf(c[f][1], 0.f));
                float2 v1 = make_float2(fmaxf(c[f][2], 0.f), fmaxf(c[f][3], 0.f));
                *(float2*)&out[(size_t)(point0 + r0)     * DOUT + n0 + cc] = v0;
                *(float2*)&out[(size_t)(point0 + r0 + 8) * DOUT + n0 + cc] = v1;
            }
        }
    }
}

// ---------------------------------------------------------------------------
extern "C" void kernel_launch(void* const* d_in, const int* in_sizes, int n_in,
                              void* d_out, int out_size)
{
    const float* X     = (const float*)d_in[0];
    const float* F     = (const float*)d_in[1];
    const int*   Nbr   = (const int*)  d_in[2];
    const float* H     = (const float*)d_in[3];
    const float* gamma = (const float*)d_in[4];
    const float* gbias = (const float*)d_in[5];
    float*       out   = (float*)d_out;

    (void)in_sizes; (void)n_in; (void)out_size;

    int dev = 0, sms = 148, maxb = 1;
    cudaGetDevice(&dev);
    cudaDeviceGetAttribute(&sms, cudaDevAttrMultiProcessorCount, dev);
    cudaOccupancyMaxActiveBlocksPerMultiprocessor(&maxb, fused_kernel, 256, 0);
    if (maxb < 1) maxb = 1;
    if (maxb > 8) maxb = 8;
    int blocks = sms * maxb;

    fused_kernel<<<blocks, 256>>>(X, F, Nbr, H, gamma, gbias, out);
}